// round 1
// baseline (speedup 1.0000x reference)
#include <cuda_runtime.h>
#include <math.h>

#define N_NODES 131072
#define N_EDGES 1048576
#define F_DIM   32
#define H_DIM   128
#define G_NUM   512

// Output layout (float32, concatenated in reference return order)
#define OUT_A   0LL         // [512,5]
#define OUT_S   2560LL      // [512,1000]
#define OUT_T   514560LL    // [512,1000]
#define OUT_ACT 1026560LL   // [512,4]
#define OUT_V   1028608LL   // [512,1]

// ---------------- scratch (static device globals; no allocation) ----------
__device__ float d_h0[N_NODES * H_DIM];    // 64 MB
__device__ float d_msg[N_NODES * H_DIM];   // 64 MB
__device__ float d_gsum[G_NUM * H_DIM];
__device__ float d_s2[G_NUM * 64];
__device__ int   d_flag64;

// ---------------- helpers -------------------------------------------------
__device__ __forceinline__ long long ldidx(const void* p, long long i, int f64) {
    if (f64) return ((const long long*)p)[i];
    return (long long)((const int*)p)[i];
}

__device__ __forceinline__ void red_add_v4(float* ptr, float a, float b, float c, float d) {
    asm volatile("red.global.add.v4.f32 [%0], {%1,%2,%3,%4};"
                 :: "l"(ptr), "f"(a), "f"(b), "f"(c), "f"(d) : "memory");
}

// ---------------- kernel 0: dtype detect ----------------------------------
__global__ void k_detect(const void* __restrict__ eidx) {
    if (threadIdx.x == 0 && blockIdx.x == 0) {
        const unsigned* p = (const unsigned*)eidx;
        int f = 1;
        for (int i = 0; i < 128; i++) {
            if (p[2 * i + 1] != 0u) { f = 0; break; }
        }
        d_flag64 = f;
    }
}

// ---------------- kernel 1: h0 = nf @ W_in; zero msg/gsum -----------------
__global__ void k_h0(const float* __restrict__ nf, const float* __restrict__ Win) {
    __shared__ float sw[F_DIM * H_DIM];   // 16 KB
    int t = threadIdx.x;                  // 256
    #pragma unroll
    for (int i = 0; i < 16; i++) sw[t + i * 256] = Win[t + i * 256];
    __syncthreads();

    int idx = blockIdx.x * 256 + t;       // < N*H
    int n = idx >> 7, j = idx & 127;
    const float* x = nf + (long long)n * F_DIM;
    float acc = 0.f;
    #pragma unroll
    for (int k = 0; k < F_DIM; k++) acc += __ldg(x + k) * sw[k * H_DIM + j];
    d_h0[idx]  = acc;
    d_msg[idx] = 0.f;
    if (idx < G_NUM * H_DIM) d_gsum[idx] = 0.f;
}

// ---------------- kernel 2: edge scatter msg[tgt] += h0[src]*w ------------
__global__ void k_edge(const void* __restrict__ eidx, const float* __restrict__ ew) {
    const int f64 = d_flag64;
    int e = blockIdx.x * 8 + (threadIdx.x >> 5);
    int lane = threadIdx.x & 31;
    long long src = ldidx(eidx, e, f64);
    long long tgt = ldidx(eidx, (long long)N_EDGES + e, f64);
    float w = __ldg(ew + e);
    float4 v = ((const float4*)(d_h0 + src * H_DIM))[lane];
    float* dst = d_msg + tgt * H_DIM + lane * 4;
    red_add_v4(dst, v.x * w, v.y * w, v.z * w, v.w * w);
}

// ---------------- kernel 3: h = relu(h0 + msg@W_msg); pool into gsum ------
// Tile: 64 rows x 128 cols, 256 threads, thread micro-tile 4x8.
__global__ void k_gemm_pool(const float* __restrict__ Wmsg, const void* __restrict__ batch) {
    __shared__ float As[32][64];    // [k][row]  8 KB
    __shared__ float Bs[32][128];   // [k][col] 16 KB
    const int f64 = d_flag64;
    int t = threadIdx.x;
    int rowBase = blockIdx.x * 64;
    int tc = t & 15, tr = t >> 4;         // col tile 0..15 (8 cols), row tile 0..15 (4 rows)

    float acc[4][8];
    #pragma unroll
    for (int i = 0; i < 4; i++)
        #pragma unroll
        for (int j = 0; j < 8; j++) acc[i][j] = 0.f;

    for (int k0 = 0; k0 < H_DIM; k0 += 32) {
        // load A tile (transposed into smem)
        {
            int r = t >> 2, kb = (t & 3) * 8;
            const float4* mrow = (const float4*)(d_msg + (long long)(rowBase + r) * H_DIM + k0 + kb);
            float4 a0 = mrow[0], a1 = mrow[1];
            As[kb + 0][r] = a0.x; As[kb + 1][r] = a0.y; As[kb + 2][r] = a0.z; As[kb + 3][r] = a0.w;
            As[kb + 4][r] = a1.x; As[kb + 5][r] = a1.y; As[kb + 6][r] = a1.z; As[kb + 7][r] = a1.w;
        }
        // load B tile
        {
            int kk = t >> 3, cb = (t & 7) * 16;
            const float4* wrow = (const float4*)(Wmsg + (long long)(k0 + kk) * H_DIM + cb);
            float4* bs = (float4*)&Bs[kk][cb];
            bs[0] = wrow[0]; bs[1] = wrow[1]; bs[2] = wrow[2]; bs[3] = wrow[3];
        }
        __syncthreads();

        #pragma unroll
        for (int kk = 0; kk < 32; kk++) {
            float4 a  = *(const float4*)&As[kk][tr * 4];
            float4 b0 = *(const float4*)&Bs[kk][tc * 8];
            float4 b1 = *(const float4*)&Bs[kk][tc * 8 + 4];
            float av[4] = {a.x, a.y, a.z, a.w};
            float bv[8] = {b0.x, b0.y, b0.z, b0.w, b1.x, b1.y, b1.z, b1.w};
            #pragma unroll
            for (int i = 0; i < 4; i++)
                #pragma unroll
                for (int j = 0; j < 8; j++) acc[i][j] += av[i] * bv[j];
        }
        __syncthreads();
    }

    // epilogue: add h0, relu, pool into per-graph sums
    int c0 = tc * 8;
    long long gid[4];
    float vals[4][8];
    #pragma unroll
    for (int i = 0; i < 4; i++) {
        int n = rowBase + tr * 4 + i;
        gid[i] = ldidx(batch, n, f64);
        const float4* h0r = (const float4*)(d_h0 + (long long)n * H_DIM + c0);
        float4 ha = h0r[0], hb = h0r[1];
        float hv[8] = {ha.x, ha.y, ha.z, ha.w, hb.x, hb.y, hb.z, hb.w};
        #pragma unroll
        for (int j = 0; j < 8; j++) vals[i][j] = fmaxf(acc[i][j] + hv[j], 0.f);
    }

    if (gid[0] == gid[1] && gid[1] == gid[2] && gid[2] == gid[3]) {
        float s[8];
        #pragma unroll
        for (int j = 0; j < 8; j++) s[j] = vals[0][j] + vals[1][j] + vals[2][j] + vals[3][j];
        float* base = d_gsum + gid[0] * H_DIM + c0;
        red_add_v4(base,     s[0], s[1], s[2], s[3]);
        red_add_v4(base + 4, s[4], s[5], s[6], s[7]);
    } else {
        #pragma unroll
        for (int i = 0; i < 4; i++) {
            float* base = d_gsum + gid[i] * H_DIM + c0;
            red_add_v4(base,     vals[i][0], vals[i][1], vals[i][2], vals[i][3]);
            red_add_v4(base + 4, vals[i][4], vals[i][5], vals[i][6], vals[i][7]);
        }
    }
}

// ---------------- kernel 4a: per-graph backbone + small heads -------------
// One block per graph, 128 threads.
__global__ void k_head_small(const void* __restrict__ batch,
                             const float* __restrict__ W1, const float* __restrict__ W2,
                             const float* __restrict__ Wa, const float* __restrict__ Wact,
                             const float* __restrict__ Wv1, const float* __restrict__ Wv2,
                             float* __restrict__ out) {
    __shared__ float sg[128], s1[128], ss[64], v1s[32];
    const int f64 = d_flag64;
    int g = blockIdx.x, t = threadIdx.x;

    // count nodes in graph g via binary search over sorted batch
    int lo = 0, hi = N_NODES;
    while (lo < hi) { int mid = (lo + hi) >> 1; if (ldidx(batch, mid, f64) < (long long)g) lo = mid + 1; else hi = mid; }
    int start = lo;
    hi = N_NODES;
    while (lo < hi) { int mid = (lo + hi) >> 1; if (ldidx(batch, mid, f64) < (long long)g + 1) lo = mid + 1; else hi = mid; }
    int cnt = lo - start;
    float inv = (cnt > 0) ? 1.f / (float)cnt : 0.f;

    sg[t] = d_gsum[g * H_DIM + t] * inv;
    __syncthreads();

    // s1 = relu(g @ (W1_top + W1_bot))   (cat([g,g]) fold)
    {
        float acc = 0.f;
        #pragma unroll 4
        for (int k = 0; k < 128; k++)
            acc += sg[k] * (__ldg(W1 + k * 128 + t) + __ldg(W1 + (k + 128) * 128 + t));
        s1[t] = fmaxf(acc, 0.f);
    }
    __syncthreads();

    // s2 = relu(s1 @ W2)  [64]
    if (t < 64) {
        float acc = 0.f;
        #pragma unroll 4
        for (int k = 0; k < 128; k++) acc += s1[k] * __ldg(W2 + k * 64 + t);
        acc = fmaxf(acc, 0.f);
        ss[t] = acc;
        d_s2[g * 64 + t] = acc;
    }
    __syncthreads();

    if (t < 5) {                       // action_type
        float acc = 0.f;
        #pragma unroll
        for (int k = 0; k < 64; k++) acc += ss[k] * __ldg(Wa + k * 5 + t);
        out[OUT_A + g * 5 + t] = acc;
    } else if (t >= 32 && t < 36) {    // activation_logits
        int j = t - 32; float acc = 0.f;
        #pragma unroll
        for (int k = 0; k < 64; k++) acc += ss[k] * __ldg(Wact + k * 4 + j);
        out[OUT_ACT + g * 4 + j] = acc;
    } else if (t >= 64 && t < 96) {    // value hidden
        int j = t - 64; float acc = 0.f;
        #pragma unroll
        for (int k = 0; k < 64; k++) acc += ss[k] * __ldg(Wv1 + k * 32 + j);
        v1s[j] = fmaxf(acc, 0.f);
    }
    __syncthreads();
    if (t == 0) {                      // value = tanh(v1 @ Wv2)
        float acc = 0.f;
        #pragma unroll
        for (int k = 0; k < 32; k++) acc += v1s[k] * __ldg(Wv2 + k);
        out[OUT_V + g] = tanhf(acc);
    }
}

// ---------------- kernel 4b: big heads (source/target logits) -------------
// block = 8 graphs x 1000 cols for one head. grid (64, 2).
__global__ void k_head_big(const float* __restrict__ Ws, const float* __restrict__ Wt,
                           float* __restrict__ out) {
    __shared__ float s2s[8][64];
    int gbase = blockIdx.x * 8;
    const float* W = blockIdx.y ? Wt : Ws;
    long long off = blockIdx.y ? OUT_T : OUT_S;
    int t = threadIdx.x;

    for (int i = t; i < 512; i += 128) s2s[i >> 6][i & 63] = d_s2[gbase * 64 + i];
    __syncthreads();

    for (int m = t; m < 1000; m += 128) {
        float acc[8];
        #pragma unroll
        for (int g8 = 0; g8 < 8; g8++) acc[g8] = 0.f;
        #pragma unroll 8
        for (int k = 0; k < 64; k++) {
            float wv = __ldg(W + k * 1000 + m);
            #pragma unroll
            for (int g8 = 0; g8 < 8; g8++) acc[g8] += s2s[g8][k] * wv;
        }
        #pragma unroll
        for (int g8 = 0; g8 < 8; g8++)
            out[off + (long long)(gbase + g8) * 1000 + m] = acc[g8];
    }
}

// ---------------- launch ---------------------------------------------------
extern "C" void kernel_launch(void* const* d_in, const int* in_sizes, int n_in,
                              void* d_out, int out_size) {
    const float* nf   = (const float*)d_in[0];
    const void*  eidx = d_in[1];
    const float* ew   = (const float*)d_in[2];
    // d_in[3] = layer_positions (unused)
    const void*  batch = d_in[4];
    // weights: robust to num_graphs scalar presence/absence (10 trailing weight arrays)
    int wb = n_in - 10;
    const float* Win  = (const float*)d_in[wb + 0];
    const float* Wmsg = (const float*)d_in[wb + 1];
    const float* W1   = (const float*)d_in[wb + 2];
    const float* W2   = (const float*)d_in[wb + 3];
    const float* Wa   = (const float*)d_in[wb + 4];
    const float* Ws   = (const float*)d_in[wb + 5];
    const float* Wt   = (const float*)d_in[wb + 6];
    const float* Wact = (const float*)d_in[wb + 7];
    const float* Wv1  = (const float*)d_in[wb + 8];
    const float* Wv2  = (const float*)d_in[wb + 9];
    float* out = (float*)d_out;

    k_detect<<<1, 32>>>(eidx);
    k_h0<<<(N_NODES * H_DIM) / 256, 256>>>(nf, Win);
    k_edge<<<N_EDGES / 8, 256>>>(eidx, ew);
    k_gemm_pool<<<N_NODES / 64, 256>>>(Wmsg, batch);
    k_head_small<<<G_NUM, 128>>>(batch, W1, W2, Wa, Wact, Wv1, Wv2, out);
    k_head_big<<<dim3(64, 2), 128>>>(Ws, Wt, out);
}